// round 11
// baseline (speedup 1.0000x reference)
#include <cuda_runtime.h>
#include <cuda_fp16.h>
#include <cstdint>

#define B_     4096
#define N_IN   512
#define H1     1536
#define H2     1536
#define N_OUT  512
#define NODES  3584
#define CAP    128           // bucket capacity per dst (Poisson(32), max ~66)
#define TBLOCKS 2048         // transpose blocks in fused setup kernel

typedef unsigned long long u64;

// ---------------- static device scratch (no allocations) ----------------
__device__ __align__(16) __half g_nvTh[NODES * B_];      // 29.4 MB fp16 node values
__device__ __align__(16) float  g_outT[N_OUT * B_];      //  8.4 MB
__device__ int  g_cnt[NODES];        // zero at load; re-zeroed by transpose_out
__device__ __align__(16) int2 g_bpack[NODES * CAP];      // (src, w-bits); slots >= cnt stay 0

// ---------------- helpers ----------------
__device__ __forceinline__ u64 pack2(float x, float y) {
    u64 r; asm("mov.b64 %0, {%1, %2};" : "=l"(r) : "f"(x), "f"(y)); return r;
}
__device__ __forceinline__ float2 unpack2(u64 v) {
    float2 f; asm("mov.b64 {%0, %1}, %2;" : "=f"(f.x), "=f"(f.y) : "l"(v)); return f;
}
__device__ __forceinline__ void ffma2(u64& acc, u64 a, u64 b) {
    asm("fma.rn.f32x2 %0, %1, %2, %0;" : "+l"(acc) : "l"(a), "l"(b));
}

// ---------------- fused setup: transpose x -> fp16 nvT  +  bucket build ----
__global__ void setup_kernel(const float* __restrict__ x,
                             const int* __restrict__ src0, const int* __restrict__ dst0,
                             const float* __restrict__ w0, int E1,
                             const int* __restrict__ src1, const int* __restrict__ dst1,
                             const float* __restrict__ w1, int E2,
                             const int* __restrict__ src2, const int* __restrict__ dst2,
                             const float* __restrict__ w2, int E3) {
    const int tid = threadIdx.x;
    if (blockIdx.x < TBLOCKS) {
        __shared__ float tile[32][33];
        const int bx = (blockIdx.x & 15) * 32;   // node dim
        const int by = (blockIdx.x >> 4) * 32;   // batch dim
        const int tx = tid & 31, ty = tid >> 5;  // 32 x 8
#pragma unroll
        for (int i = 0; i < 32; i += 8)
            tile[ty + i][tx] = x[(size_t)(by + ty + i) * N_IN + bx + tx];
        __syncthreads();
#pragma unroll
        for (int i = 0; i < 32; i += 8)
            g_nvTh[(size_t)(bx + ty + i) * B_ + by + tx] = __float2half(tile[tx][ty + i]);
        return;
    }
    int i0 = ((blockIdx.x - TBLOCKS) * 256 + tid) * 4;
    const int Etot = E1 + E2 + E3;
    if (i0 >= Etot) return;
    const int *sp, *dp; const float* wp; int dbase, j0;
    if (i0 < E1)           { sp = src0; dp = dst0; wp = w0; dbase = 0;       j0 = i0; }
    else if (i0 < E1 + E2) { sp = src1; dp = dst1; wp = w1; dbase = H1;      j0 = i0 - E1; }
    else                   { sp = src2; dp = dst2; wp = w2; dbase = H1 + H2; j0 = i0 - E1 - E2; }
    int4   s = *reinterpret_cast<const int4*>(sp + j0);
    int4   d = *reinterpret_cast<const int4*>(dp + j0);
    float4 w = *reinterpret_cast<const float4*>(wp + j0);
#pragma unroll
    for (int k = 0; k < 4; k++) {
        int sk = (&s.x)[k];
        int dk = dbase + (&d.x)[k];
        float wk = (&w.x)[k];
        int c = atomicAdd(&g_cnt[dk], 1);
        if (c < CAP)
            g_bpack[(size_t)dk * CAP + c] = make_int2(sk, __float_as_int(wk));
    }
}

// ---------------- output transpose + cnt reset for next call ----------------
__global__ void transpose_out_kernel(float* __restrict__ out) {
    if (blockIdx.x == 0 && blockIdx.y == 0) {
        for (int i = threadIdx.y * 32 + threadIdx.x; i < NODES; i += 256)
            g_cnt[i] = 0;
    }
    __shared__ float tile[32][33];
    const int bd = blockIdx.x * 32;
    const int bb = blockIdx.y * 32;
    const int tx = threadIdx.x, ty = threadIdx.y;
#pragma unroll
    for (int i = 0; i < 32; i += 8)
        tile[ty + i][tx] = g_outT[(size_t)(bd + ty + i) * B_ + bb + tx];
    __syncthreads();
#pragma unroll
    for (int i = 0; i < 32; i += 8)
        out[(size_t)(bb + ty + i) * N_OUT + bd + tx] = tile[tx][ty + i];
}

// ---------------- SMEM-staged level kernel (v2) ----------------
// Grid (B_/NCOLS segs, dst-chunks). 256 threads. Phase A: stage fp16 rows ->
// fp32 SMEM (convert once). Phase B: 2 lanes per dst, CPL = NCOLS/2 cols per
// lane, pure LDS.128 + FFMA2 inner loop. Uniform work per CTA (all CTAs of a
// level process DCHUNK dsts). Buckets zero-padded to multiples of 4.
template <int ROWS, int NCOLS, int DCHUNK, int CBASE, bool F32OUT>
__global__ void __launch_bounds__(256)
level_smem_kernel(__half* __restrict__ outh, float* __restrict__ outf) {
    extern __shared__ __align__(16) float sval[];    // [ROWS][NCOLS]
    constexpr int CPL = NCOLS / 2;                   // cols per lane (8 or 4)
    constexpr int NACC = CPL / 2;                    // u64 accumulators
    const int c0 = blockIdx.x * NCOLS;
    const int dbase = blockIdx.y * DCHUNK;
    const int t = threadIdx.x;

    // ---- Phase A: stage + widen to fp32 ----
    for (int r = t; r < ROWS; r += 256) {
        const __half* src = g_nvTh + (size_t)r * B_ + c0;
        float* drow = sval + r * NCOLS;
#pragma unroll
        for (int q = 0; q < NCOLS / 8; q++) {
            uint4 h = *reinterpret_cast<const uint4*>(src + q * 8);
            float2 f0 = __half22float2(*reinterpret_cast<__half2*>(&h.x));
            float2 f1 = __half22float2(*reinterpret_cast<__half2*>(&h.y));
            float2 f2 = __half22float2(*reinterpret_cast<__half2*>(&h.z));
            float2 f3 = __half22float2(*reinterpret_cast<__half2*>(&h.w));
            *reinterpret_cast<float4*>(drow + q * 8)     = make_float4(f0.x, f0.y, f1.x, f1.y);
            *reinterpret_cast<float4*>(drow + q * 8 + 4) = make_float4(f2.x, f2.y, f3.x, f3.y);
        }
    }
    __syncthreads();

    // ---- Phase B ----
    const int dloc = t >> 1;        // 0..127: dst within pass
    const int sub  = t & 1;         // which half of the column tile

#pragma unroll 1
    for (int p = 0; p < DCHUNK; p += 128) {
        const int d = dbase + p + dloc;
        int cnt = g_cnt[CBASE + d];
        if (cnt > CAP) cnt = CAP;
        const int cntUp = (cnt + 3) & ~3;
        const int2* bp = g_bpack + (size_t)(CBASE + d) * CAP;

        u64 acc[NACC];
#pragma unroll
        for (int j = 0; j < NACC; j++) acc[j] = 0;

        auto doEdge = [&](int s, int wb) {
            const float* row = sval + s * NCOLS + sub * CPL;
            float wf = __int_as_float(wb);
            u64 W = pack2(wf, wf);
            if (CPL == 8) {
                ulonglong2 v0 = *reinterpret_cast<const ulonglong2*>(row);
                ulonglong2 v1 = *reinterpret_cast<const ulonglong2*>(row + 4);
                ffma2(acc[0], W, v0.x); ffma2(acc[1], W, v0.y);
                ffma2(acc[NACC > 2 ? 2 : 0], W, v1.x);
                ffma2(acc[NACC > 3 ? 3 : 0], W, v1.y);
            } else {
                ulonglong2 v0 = *reinterpret_cast<const ulonglong2*>(row);
                ffma2(acc[0], W, v0.x); ffma2(acc[1], W, v0.y);
            }
        };

        for (int e = 0; e < cntUp; e += 4) {
            int4 m0 = *reinterpret_cast<const int4*>(bp + e);       // s0,w0,s1,w1
            int4 m1 = *reinterpret_cast<const int4*>(bp + e + 2);   // s2,w2,s3,w3
            doEdge(m0.x, m0.y);
            doEdge(m0.z, m0.w);
            doEdge(m1.x, m1.y);
            doEdge(m1.z, m1.w);
        }

        // ---- relu + store ----
        float r[CPL];
#pragma unroll
        for (int j = 0; j < NACC; j++) {
            float2 f = unpack2(acc[j]);
            r[2 * j]     = fmaxf(f.x, 0.f);
            r[2 * j + 1] = fmaxf(f.y, 0.f);
        }
        const int cc = c0 + sub * CPL;
        if (F32OUT) {
            // CPL == 4: one float4
            *reinterpret_cast<float4*>(outf + (size_t)d * B_ + cc) =
                make_float4(r[0], r[1], r[2], r[3]);
        } else if (CPL == 8) {
            uint4 o; __half2 h;
            h = __floats2half2_rn(r[0], r[1]); o.x = *reinterpret_cast<uint32_t*>(&h);
            h = __floats2half2_rn(r[2], r[3]); o.y = *reinterpret_cast<uint32_t*>(&h);
            h = __floats2half2_rn(r[4], r[5]); o.z = *reinterpret_cast<uint32_t*>(&h);
            h = __floats2half2_rn(r[6], r[7]); o.w = *reinterpret_cast<uint32_t*>(&h);
            *reinterpret_cast<uint4*>(outh + (size_t)d * B_ + cc) = o;
        } else {
            uint2 o; __half2 h;
            h = __floats2half2_rn(r[0], r[1]); o.x = *reinterpret_cast<uint32_t*>(&h);
            h = __floats2half2_rn(r[2], r[3]); o.y = *reinterpret_cast<uint32_t*>(&h);
            *reinterpret_cast<uint2*>(outh + (size_t)d * B_ + cc) = o;
        }
    }
}

// ---------------- launch ----------------
extern "C" void kernel_launch(void* const* d_in, const int* in_sizes, int n_in,
                              void* d_out, int out_size) {
    const float* x    = (const float*)d_in[0];
    const int*   src0 = (const int*)  d_in[1];
    const int*   dst0 = (const int*)  d_in[2];
    const float* w0   = (const float*)d_in[3];
    const int*   src1 = (const int*)  d_in[4];
    const int*   dst1 = (const int*)  d_in[5];
    const float* w1   = (const float*)d_in[6];
    const int*   src2 = (const int*)  d_in[7];
    const int*   dst2 = (const int*)  d_in[8];
    const float* w2   = (const float*)d_in[9];
    float* out = (float*)d_out;

    __half* pnvTh; cudaGetSymbolAddress((void**)&pnvTh, g_nvTh);
    float*  poutT; cudaGetSymbolAddress((void**)&poutT, g_outT);

    const int E1 = in_sizes[1], E2 = in_sizes[4], E3 = in_sizes[7];
    const int Etot = E1 + E2 + E3;

    // SMEM sizes (fp32 tiles)
    constexpr int SM1 = 512  * 16 * 4;   //  32 KB
    constexpr int SM2 = 2048 * 8  * 4;   //  64 KB
    constexpr int SM3 = 3584 * 8  * 4;   // 112 KB
    cudaFuncSetAttribute((const void*)level_smem_kernel<512,  16, 512, 0,       false>,
                         cudaFuncAttributeMaxDynamicSharedMemorySize, SM1);
    cudaFuncSetAttribute((const void*)level_smem_kernel<2048, 8,  768, H1,      false>,
                         cudaFuncAttributeMaxDynamicSharedMemorySize, SM2);
    cudaFuncSetAttribute((const void*)level_smem_kernel<3584, 8,  512, H1 + H2, true>,
                         cudaFuncAttributeMaxDynamicSharedMemorySize, SM3);

    // 1) fused setup: transpose x (fp32->fp16) + build edge buckets
    {
        int bucketBlocks = (Etot + 1023) / 1024;
        setup_kernel<<<TBLOCKS + bucketBlocks, 256>>>(
            x, src0, dst0, w0, E1, src1, dst1, w1, E2, src2, dst2, w2, E3);
    }

    // 2) SMEM-staged levels (uniform per-CTA work, multiple CTAs/SM)
    //    lvl1: 16-col tiles, 3 dst-chunks of 512  -> grid (256, 3)
    level_smem_kernel<512,  16, 512, 0,       false><<<dim3(B_ / 16, 3), 256, SM1>>>(
        pnvTh + (size_t)N_IN * B_, nullptr);
    //    lvl2: 8-col tiles, 2 dst-chunks of 768   -> grid (512, 2)
    level_smem_kernel<2048, 8,  768, H1,      false><<<dim3(B_ / 8, 2), 256, SM2>>>(
        pnvTh + (size_t)(N_IN + H1) * B_, nullptr);
    //    lvl3: 8-col tiles, 1 chunk of 512        -> grid (512, 1)
    level_smem_kernel<3584, 8,  512, H1 + H2, true ><<<dim3(B_ / 8, 1), 256, SM3>>>(
        nullptr, poutT);

    // 3) transpose result to [B, N_OUT] (+ reset g_cnt for next call)
    transpose_out_kernel<<<dim3(N_OUT / 32, B_ / 32), dim3(32, 8)>>>(out);
}

// round 12
// speedup vs baseline: 2.2956x; 2.2956x over previous
#include <cuda_runtime.h>
#include <cuda_fp16.h>
#include <cstdint>

#define B_     4096
#define N_IN   512
#define H1     1536
#define H2     1536
#define N_OUT  512
#define NODES  3584
#define CAP    128           // bucket capacity per dst (Poisson(32), max ~66)
#define C      32            // batch columns per CTA
#define NSEG   (B_ / C)      // 128 CTAs

typedef unsigned long long u64;

// ---------------- static device scratch (no allocations) ----------------
__device__ int  g_cnt[NODES];
__device__ __align__(16) int2 g_bpack[NODES * CAP];   // (src, w-bits); slots >= cnt stay 0

// ---------------- f32x2 helpers ----------------
__device__ __forceinline__ u64 pack2(float x, float y) {
    u64 r; asm("mov.b64 %0, {%1, %2};" : "=l"(r) : "f"(x), "f"(y)); return r;
}
__device__ __forceinline__ float2 unpack2(u64 v) {
    float2 f; asm("mov.b64 {%0, %1}, %2;" : "=f"(f.x), "=f"(f.y) : "l"(v)); return f;
}
__device__ __forceinline__ void ffma2(u64& acc, u64 a, u64 b) {
    asm("fma.rn.f32x2 %0, %1, %2, %0;" : "+l"(acc) : "l"(a), "l"(b));
}

// ---------------- setup ----------------
__global__ void zero_cnt_kernel() {
    int i = blockIdx.x * 256 + threadIdx.x;
    if (i < NODES) g_cnt[i] = 0;
}

__global__ void bucket_kernel(const int* __restrict__ src0, const int* __restrict__ dst0,
                              const float* __restrict__ w0, int E1,
                              const int* __restrict__ src1, const int* __restrict__ dst1,
                              const float* __restrict__ w1, int E2,
                              const int* __restrict__ src2, const int* __restrict__ dst2,
                              const float* __restrict__ w2, int E3) {
    int i0 = (blockIdx.x * 256 + threadIdx.x) * 4;
    const int Etot = E1 + E2 + E3;
    if (i0 >= Etot) return;
    const int *sp, *dp; const float* wp; int dbase, j0;
    if (i0 < E1)           { sp = src0; dp = dst0; wp = w0; dbase = 0;       j0 = i0; }
    else if (i0 < E1 + E2) { sp = src1; dp = dst1; wp = w1; dbase = H1;      j0 = i0 - E1; }
    else                   { sp = src2; dp = dst2; wp = w2; dbase = H1 + H2; j0 = i0 - E1 - E2; }
    int4   s = *reinterpret_cast<const int4*>(sp + j0);
    int4   d = *reinterpret_cast<const int4*>(dp + j0);
    float4 w = *reinterpret_cast<const float4*>(wp + j0);
#pragma unroll
    for (int k = 0; k < 4; k++) {
        int sk = (&s.x)[k];
        int dk = dbase + (&d.x)[k];
        float wk = (&w.x)[k];
        int c = atomicAdd(&g_cnt[dk], 1);
        if (c < CAP)
            g_bpack[(size_t)dk * CAP + c] = make_int2(sk, __float_as_int(wk));
    }
}

// ---------------- fused 3-level kernel ----------------
// sval layout: __half rows, row = global node id, 32 halves (64B) per row.
//   rows [0,512)   : x tile (fp16)
//   rows [512,2048): h1
//   rows [2048,3584): h2
// A-phase fp32 staging at byte 65536 (dead before L1 writes reach it).
// h3 staging at bytes [0, 33280) after L3 compute (x dead by then).
__device__ __forceinline__ u64 gather_acc(const __half* sval, int ci, int j) {
    int cnt = g_cnt[ci];
    if (cnt > CAP) cnt = CAP;
    const int up = (cnt + 1) & ~1;
    const int2* bp = g_bpack + (size_t)ci * CAP;
    u64 acc = 0;
    for (int e = 0; e < up; e += 2) {
        int4 m = *reinterpret_cast<const int4*>(bp + e);   // s0,w0,s1,w1
        __half2 p0 = *reinterpret_cast<const __half2*>(sval + m.x * C + 2 * j);
        __half2 p1 = *reinterpret_cast<const __half2*>(sval + m.z * C + 2 * j);
        float2 f0 = __half22float2(p0);
        float2 f1 = __half22float2(p1);
        float w0 = __int_as_float(m.y), w1 = __int_as_float(m.w);
        ffma2(acc, pack2(w0, w0), pack2(f0.x, f0.y));
        ffma2(acc, pack2(w1, w1), pack2(f1.x, f1.y));
    }
    return acc;
}

__global__ void __launch_bounds__(1024, 1)
fused_kernel(const float* __restrict__ x, float* __restrict__ out) {
    extern __shared__ __align__(16) __half sval[];
    const int seg  = blockIdx.x;
    const int tid  = threadIdx.x;
    const int w    = tid >> 5;
    const int lane = tid & 31;
    const int h    = lane >> 4;     // half-warp: which dst of the pair
    const int j    = lane & 15;     // covers cols 2j, 2j+1

    // ---- Phase A1: coalesced x load -> fp32 staging (padded rows of 516 words)
    float* stage = reinterpret_cast<float*>(reinterpret_cast<char*>(sval) + 65536);
    {
        const float4* xs = reinterpret_cast<const float4*>(x + (size_t)seg * 32 * 512);
#pragma unroll
        for (int idx = tid; idx < 32 * 128; idx += 1024) {
            int b = idx >> 7, q = idx & 127;
            float4 v = xs[idx];
            *reinterpret_cast<float4*>(stage + b * 516 + q * 4) = v;
        }
    }
    __syncthreads();
    // ---- Phase A2: transpose staging -> fp16 sval rows [0,512)
    {
        // warp covers 2 node-rows; lane j2=lane&15 writes word (b=2*j2, 2*j2+1)
        for (int nb = w * 2 + (lane >> 4); nb < 512; nb += 64) {
            int j2 = lane & 15;
            float b0 = stage[(2 * j2) * 516 + nb];
            float b1 = stage[(2 * j2 + 1) * 516 + nb];
            *reinterpret_cast<__half2*>(sval + nb * C + 2 * j2) = __floats2half2_rn(b0, b1);
        }
    }
    __syncthreads();

    // ---- Level 1: dsts [0,H1), smem rows 512+d, cnt base 0
#pragma unroll 1
    for (int p = 0; p < 24; p++) {
        int d = 2 * (w + 32 * p) + h;
        u64 acc = gather_acc(sval, d, j);
        float2 f = unpack2(acc);
        *reinterpret_cast<__half2*>(sval + (512 + d) * C + 2 * j) =
            __floats2half2_rn(fmaxf(f.x, 0.f), fmaxf(f.y, 0.f));
    }
    __syncthreads();

    // ---- Level 2: dsts [0,H2), smem rows 2048+d, cnt base H1
#pragma unroll 1
    for (int p = 0; p < 24; p++) {
        int d = 2 * (w + 32 * p) + h;
        u64 acc = gather_acc(sval, H1 + d, j);
        float2 f = unpack2(acc);
        *reinterpret_cast<__half2*>(sval + (2048 + d) * C + 2 * j) =
            __floats2half2_rn(fmaxf(f.x, 0.f), fmaxf(f.y, 0.f));
    }
    __syncthreads();

    // ---- Level 3: dsts [0,512), keep accumulators in registers
    u64 acc3[8];
#pragma unroll 1
    for (int p = 0; p < 8; p++) {
        int d = 2 * (w + 32 * p) + h;
        acc3[p] = gather_acc(sval, H1 + H2 + d, j);
    }
    __syncthreads();   // all gathers done; safe to overwrite sval

    // ---- Stage h3 as fp16 [b][d], half-stride 520 (byte stride 1040)
#pragma unroll
    for (int p = 0; p < 8; p++) {
        int d = 2 * (w + 32 * p) + h;
        float2 f = unpack2(acc3[p]);
        sval[(2 * j) * 520 + d]     = __float2half(fmaxf(f.x, 0.f));
        sval[(2 * j + 1) * 520 + d] = __float2half(fmaxf(f.y, 0.f));
    }
    __syncthreads();

    // ---- Coalesced fp32 output store: out[b][d]
    {
        int b = tid >> 5, k = tid & 31, d0 = k * 16;
        const __half* src = sval + b * 520 + d0;
        uint4 u0 = *reinterpret_cast<const uint4*>(src);
        uint4 u1 = *reinterpret_cast<const uint4*>(src + 8);
        float* po = out + (size_t)(seg * 32 + b) * 512 + d0;
        const __half2* hh0 = reinterpret_cast<const __half2*>(&u0);
        const __half2* hh1 = reinterpret_cast<const __half2*>(&u1);
#pragma unroll
        for (int q = 0; q < 4; q++) {
            float2 a = __half22float2(hh0[q]);
            po[2 * q]     = a.x;
            po[2 * q + 1] = a.y;
        }
#pragma unroll
        for (int q = 0; q < 4; q++) {
            float2 a = __half22float2(hh1[q]);
            po[8 + 2 * q]     = a.x;
            po[8 + 2 * q + 1] = a.y;
        }
    }
}

// ---------------- launch ----------------
extern "C" void kernel_launch(void* const* d_in, const int* in_sizes, int n_in,
                              void* d_out, int out_size) {
    const float* x    = (const float*)d_in[0];
    const int*   src0 = (const int*)  d_in[1];
    const int*   dst0 = (const int*)  d_in[2];
    const float* w0   = (const float*)d_in[3];
    const int*   src1 = (const int*)  d_in[4];
    const int*   dst1 = (const int*)  d_in[5];
    const float* w1   = (const float*)d_in[6];
    const int*   src2 = (const int*)  d_in[7];
    const int*   dst2 = (const int*)  d_in[8];
    const float* w2   = (const float*)d_in[9];
    float* out = (float*)d_out;

    const int E1 = in_sizes[1], E2 = in_sizes[4], E3 = in_sizes[7];
    const int Etot = E1 + E2 + E3;

    constexpr int SMEM = NODES * C * 2;   // 229376 bytes
    cudaFuncSetAttribute(fused_kernel, cudaFuncAttributeMaxDynamicSharedMemorySize, SMEM);

    // 1) reset bucket counters (must precede atomics each call)
    zero_cnt_kernel<<<(NODES + 255) / 256, 256>>>();

    // 2) build zero-padded per-dst edge buckets
    bucket_kernel<<<(Etot + 1023) / 1024, 256>>>(
        src0, dst0, w0, E1, src1, dst1, w1, E2, src2, dst2, w2, E3);

    // 3) fused 3-level forward pass, one CTA per 32-column batch slice
    fused_kernel<<<NSEG, 1024, SMEM>>>(x, out);
}

// round 13
// speedup vs baseline: 4.1734x; 1.8180x over previous
#include <cuda_runtime.h>
#include <cuda_fp16.h>
#include <cstdint>

#define B_     4096
#define N_IN   512
#define H1     1536
#define H2     1536
#define N_OUT  512
#define NODES  3584          // N_IN + H1 + H2
#define CAP    128           // bucket capacity per dst (Poisson(32), max ~66)
#define TBLOCKS 2048         // transpose blocks in fused setup kernel (16 x 128)

typedef unsigned long long u64;

// ---------------- static device scratch (no allocations) ----------------
__device__ __align__(16) __half g_nvTh[NODES * B_];      // 29.4 MB node values, fp16
__device__ __align__(16) __half g_outTh[N_OUT * B_];     //  4.2 MB lvl3 result, fp16
__device__ int  g_cnt[NODES];        // zero at load; re-zeroed by transpose_out
__device__ __align__(16) int2 g_bpack[NODES * CAP];      // (src, w-bits); slots >= cnt stay 0

// ---------------- packed f32x2 helpers ----------------
__device__ __forceinline__ u64 pack2(float x, float y) {
    u64 r; asm("mov.b64 %0, {%1, %2};" : "=l"(r) : "f"(x), "f"(y)); return r;
}
__device__ __forceinline__ float2 unpack2(u64 v) {
    float2 f; asm("mov.b64 {%0, %1}, %2;" : "=f"(f.x), "=f"(f.y) : "l"(v)); return f;
}
__device__ __forceinline__ void ffma2(u64& acc, u64 a, u64 b) {
    asm("fma.rn.f32x2 %0, %1, %2, %0;" : "+l"(acc) : "l"(a), "l"(b));
}
__device__ __forceinline__ u64 cvt2(uint32_t h2) {
    float2 f = __half22float2(*reinterpret_cast<const __half2*>(&h2));
    return pack2(f.x, f.y);
}

// ---------------- fused setup: transpose x -> fp16 nvT  +  bucket build ----
__global__ void setup_kernel(const float* __restrict__ x,
                             const int* __restrict__ src0, const int* __restrict__ dst0,
                             const float* __restrict__ w0, int E1,
                             const int* __restrict__ src1, const int* __restrict__ dst1,
                             const float* __restrict__ w1, int E2,
                             const int* __restrict__ src2, const int* __restrict__ dst2,
                             const float* __restrict__ w2, int E3) {
    const int tid = threadIdx.x;
    if (blockIdx.x < TBLOCKS) {
        __shared__ float tile[32][33];
        const int bx = (blockIdx.x & 15) * 32;   // node dim
        const int by = (blockIdx.x >> 4) * 32;   // batch dim
        const int tx = tid & 31, ty = tid >> 5;  // 32 x 8
#pragma unroll
        for (int i = 0; i < 32; i += 8)
            tile[ty + i][tx] = x[(size_t)(by + ty + i) * N_IN + bx + tx];
        __syncthreads();
#pragma unroll
        for (int i = 0; i < 32; i += 8)
            g_nvTh[(size_t)(bx + ty + i) * B_ + by + tx] = __float2half(tile[tx][ty + i]);
        return;
    }
    // ---- bucket part: 4 consecutive edges per thread ----
    int i0 = ((blockIdx.x - TBLOCKS) * 256 + tid) * 4;
    const int Etot = E1 + E2 + E3;
    if (i0 >= Etot) return;
    const int *sp, *dp; const float* wp; int dbase, j0;
    if (i0 < E1)           { sp = src0; dp = dst0; wp = w0; dbase = 0;       j0 = i0; }
    else if (i0 < E1 + E2) { sp = src1; dp = dst1; wp = w1; dbase = H1;      j0 = i0 - E1; }
    else                   { sp = src2; dp = dst2; wp = w2; dbase = H1 + H2; j0 = i0 - E1 - E2; }
    int4   s = *reinterpret_cast<const int4*>(sp + j0);
    int4   d = *reinterpret_cast<const int4*>(dp + j0);
    float4 w = *reinterpret_cast<const float4*>(wp + j0);
#pragma unroll
    for (int k = 0; k < 4; k++) {
        int sk = (&s.x)[k];
        int dk = dbase + (&d.x)[k];
        float wk = (&w.x)[k];
        int c = atomicAdd(&g_cnt[dk], 1);
        if (c < CAP)
            g_bpack[(size_t)dk * CAP + c] = make_int2(sk, __float_as_int(wk));
    }
}

// ---------------- output transpose (fp16 -> fp32) + cnt reset ----------------
__global__ void transpose_out_kernel(float* __restrict__ out) {
    if (blockIdx.x == 0 && blockIdx.y == 0) {
        for (int i = threadIdx.y * 32 + threadIdx.x; i < NODES; i += 256)
            g_cnt[i] = 0;
    }
    __shared__ float tile[32][33];
    const int bd = blockIdx.x * 32;
    const int bb = blockIdx.y * 32;
    const int tx = threadIdx.x, ty = threadIdx.y;
#pragma unroll
    for (int i = 0; i < 32; i += 8)
        tile[ty + i][tx] = __half2float(g_outTh[(size_t)(bd + ty + i) * B_ + bb + tx]);
    __syncthreads();
#pragma unroll
    for (int i = 0; i < 32; i += 8)
        out[(size_t)(bb + ty + i) * N_OUT + bd + tx] = tile[tx][ty + i];
}

// ---------------- sparse level kernel (R8-proven shape) ----------------
// NSTRIP=2: one CTA per dst, thread owns strips at c0 and c0+2048 (grid (H,1)).
// NSTRIP=1: grid (H,2), thread owns 8 cols in its segment.
// 4-edge unroll; fp16 values, f32x2 accumulate; fp16 output.
__device__ __forceinline__ void strip_fma(u64* a, u64 W, uint4 v) {
    ffma2(a[0], W, cvt2(v.x));
    ffma2(a[1], W, cvt2(v.y));
    ffma2(a[2], W, cvt2(v.z));
    ffma2(a[3], W, cvt2(v.w));
}

template <int NSTRIP>
__global__ void __launch_bounds__(256)
level_kernel(int cbase, __half* __restrict__ outh) {
    const int d = blockIdx.x;
    const int t = threadIdx.x;

    int cnt = g_cnt[cbase + d];
    if (cnt > CAP) cnt = CAP;
    const int2* bp = g_bpack + (size_t)(cbase + d) * CAP;

    const int c0 = (NSTRIP == 2) ? t * 8 : blockIdx.y * 2048 + t * 8;
    const __half* __restrict__ nvTh = g_nvTh;

    u64 acc[NSTRIP][4];
#pragma unroll
    for (int s = 0; s < NSTRIP; s++)
#pragma unroll
        for (int j = 0; j < 4; j++) acc[s][j] = 0;

    int e = 0;
    // ---- 4-edge unrolled main loop
    for (; e + 4 <= cnt; e += 4) {
        int4 m0 = *reinterpret_cast<const int4*>(bp + e);       // s0,w0,s1,w1
        int4 m1 = *reinterpret_cast<const int4*>(bp + e + 2);   // s2,w2,s3,w3
        const __half* r0 = nvTh + (size_t)m0.x * B_ + c0;
        const __half* r1 = nvTh + (size_t)m0.z * B_ + c0;
        const __half* r2 = nvTh + (size_t)m1.x * B_ + c0;
        const __half* r3 = nvTh + (size_t)m1.z * B_ + c0;
        uint4 v[4][NSTRIP];
#pragma unroll
        for (int s = 0; s < NSTRIP; s++) {
            v[0][s] = *reinterpret_cast<const uint4*>(r0 + s * 2048);
            v[1][s] = *reinterpret_cast<const uint4*>(r1 + s * 2048);
            v[2][s] = *reinterpret_cast<const uint4*>(r2 + s * 2048);
            v[3][s] = *reinterpret_cast<const uint4*>(r3 + s * 2048);
        }
        u64 W0 = pack2(__int_as_float(m0.y), __int_as_float(m0.y));
        u64 W1 = pack2(__int_as_float(m0.w), __int_as_float(m0.w));
        u64 W2 = pack2(__int_as_float(m1.y), __int_as_float(m1.y));
        u64 W3 = pack2(__int_as_float(m1.w), __int_as_float(m1.w));
#pragma unroll
        for (int s = 0; s < NSTRIP; s++) {
            strip_fma(acc[s], W0, v[0][s]);
            strip_fma(acc[s], W1, v[1][s]);
            strip_fma(acc[s], W2, v[2][s]);
            strip_fma(acc[s], W3, v[3][s]);
        }
    }
    // ---- remainder
    for (; e < cnt; e++) {
        int2 ep = bp[e];
        const __half* r0 = nvTh + (size_t)ep.x * B_ + c0;
        u64 W0 = pack2(__int_as_float(ep.y), __int_as_float(ep.y));
#pragma unroll
        for (int s = 0; s < NSTRIP; s++) {
            uint4 v0 = *reinterpret_cast<const uint4*>(r0 + s * 2048);
            strip_fma(acc[s], W0, v0);
        }
    }

    // ---- relu + fp16 store ----
#pragma unroll
    for (int s = 0; s < NSTRIP; s++) {
        float r[8];
#pragma unroll
        for (int j = 0; j < 4; j++) {
            float2 f = unpack2(acc[s][j]);
            r[2 * j]     = fmaxf(f.x, 0.f);
            r[2 * j + 1] = fmaxf(f.y, 0.f);
        }
        const int cc = c0 + s * 2048;
        uint4 o; __half2 h;
        h = __floats2half2_rn(r[0], r[1]); o.x = *reinterpret_cast<uint32_t*>(&h);
        h = __floats2half2_rn(r[2], r[3]); o.y = *reinterpret_cast<uint32_t*>(&h);
        h = __floats2half2_rn(r[4], r[5]); o.z = *reinterpret_cast<uint32_t*>(&h);
        h = __floats2half2_rn(r[6], r[7]); o.w = *reinterpret_cast<uint32_t*>(&h);
        *reinterpret_cast<uint4*>(outh + (size_t)d * B_ + cc) = o;
    }
}

// ---------------- launch ----------------
extern "C" void kernel_launch(void* const* d_in, const int* in_sizes, int n_in,
                              void* d_out, int out_size) {
    const float* x    = (const float*)d_in[0];
    const int*   src0 = (const int*)  d_in[1];
    const int*   dst0 = (const int*)  d_in[2];
    const float* w0   = (const float*)d_in[3];
    const int*   src1 = (const int*)  d_in[4];
    const int*   dst1 = (const int*)  d_in[5];
    const float* w1   = (const float*)d_in[6];
    const int*   src2 = (const int*)  d_in[7];
    const int*   dst2 = (const int*)  d_in[8];
    const float* w2   = (const float*)d_in[9];
    float* out = (float*)d_out;

    __half* pnvTh;  cudaGetSymbolAddress((void**)&pnvTh,  g_nvTh);
    __half* poutTh; cudaGetSymbolAddress((void**)&poutTh, g_outTh);

    const int E1 = in_sizes[1], E2 = in_sizes[4], E3 = in_sizes[7];
    const int Etot = E1 + E2 + E3;

    // 1) fused setup: transpose x (fp32->fp16) + build edge buckets
    {
        int bucketBlocks = (Etot + 1023) / 1024;
        setup_kernel<<<TBLOCKS + bucketBlocks, 256>>>(
            x, src0, dst0, w0, E1, src1, dst1, w1, E2, src2, dst2, w2, E3);
    }

    // 2) sparse levels
    //    levels 1/2: one CTA per dst (16 cols/thread)
    level_kernel<2><<<H1, 256>>>(0,  pnvTh + (size_t)N_IN * B_);
    level_kernel<2><<<H2, 256>>>(H1, pnvTh + (size_t)(N_IN + H1) * B_);
    //    level 3: grid (512, 2), fp16 result to outTh
    level_kernel<1><<<dim3(N_OUT, 2), 256>>>(H1 + H2, poutTh);

    // 3) transpose fp16 result to fp32 [B, N_OUT] (+ reset g_cnt for next call)
    transpose_out_kernel<<<dim3(N_OUT / 32, B_ / 32), dim3(32, 8)>>>(out);
}